// round 2
// baseline (speedup 1.0000x reference)
#include <cuda_runtime.h>

// out[b,s,d] = x[b,s,d] + enc(s,d)
//   enc(s,d) = sin(s / 10000^(d/D)) if d even else cos(s / 10000^(d/D))
// Shapes: B=8, S=4096, D=1024, fp32. Pure streaming: 268 MB traffic, HBM-bound.
//
// R2 changes vs R1 (36us kernel, DRAM 75.4%, regs=58, occ 39.8%):
//  - enc computed FIRST (depends only on idx4), then batch loop split 2x4
//    to halve live float4 registers -> higher occupancy -> more outstanding
//    loads chip-wide.
//  - __ldcs/__stcs streaming (evict-first) hints: zero reuse, don't thrash L2.

#define B_ 8
#define S_ 4096
#define D_ 1024
#define SD4_ ((S_ * D_) / 4)   // 1,048,576 float4 tiles per batch slice

__global__ __launch_bounds__(256) void pe_add_kernel(
    const float4* __restrict__ x, float4* __restrict__ out)
{
    const int idx4 = blockIdx.x * blockDim.x + threadIdx.x;   // [0, SD4_)
    const int d0   = (idx4 & (D_ / 4 - 1)) << 2;              // element column in D
    const float sf = (float)(idx4 >> 8);                      // D_/4 = 256

    // Encoding float4, computed once per (s, d0..d0+3).
    // angle(d) = s * 10000^(-d/D) = s * exp2(-d * log2(1e4)/D)
    const float c = -(13.287712379549449f / 1024.0f);
    const float a0 = sf * exp2f((float)(d0 + 0) * c);
    const float a1 = sf * exp2f((float)(d0 + 1) * c);
    const float a2 = sf * exp2f((float)(d0 + 2) * c);
    const float a3 = sf * exp2f((float)(d0 + 3) * c);
    const float e0 = sinf(a0);   // even d -> sin
    const float e1 = cosf(a1);   // odd d  -> cos
    const float e2 = sinf(a2);
    const float e3 = cosf(a3);

    // Two phases of 4 batches: 4 float4 live at a time (reg pressure ~40),
    // loads front-batched within each phase (MLP=4/phase, stores of phase 0
    // overlap loads of phase 1).
#pragma unroll
    for (int h = 0; h < 2; h++) {
        float4 v[4];
#pragma unroll
        for (int b = 0; b < 4; b++)
            v[b] = __ldcs(x + (long long)(h * 4 + b) * SD4_ + idx4);
#pragma unroll
        for (int b = 0; b < 4; b++) {
            float4 r = v[b];
            r.x += e0; r.y += e1; r.z += e2; r.w += e3;
            __stcs(out + (long long)(h * 4 + b) * SD4_ + idx4, r);
        }
    }
}

extern "C" void kernel_launch(void* const* d_in, const int* in_sizes, int n_in,
                              void* d_out, int out_size)
{
    const float4* x = (const float4*)d_in[0];
    float4* out = (float4*)d_out;
    pe_add_kernel<<<SD4_ / 256, 256>>>(x, out);
}

// round 3
// speedup vs baseline: 1.0368x; 1.0368x over previous
#include <cuda_runtime.h>

// out[b,s,d] = x[b,s,d] + enc(s,d)
//   enc(s,d) = sin(s / 10000^(d/D)) if d even else cos(s / 10000^(d/D))
// Shapes: B=8, S=4096, D=1024, fp32. Pure streaming, 268 MB traffic.
//
// R3: merge of R1 (MLP=8 front-batched loads, 36.0us) and R2 (__ldcs/__stcs
// streaming hints, 36.4us). Evidence from R1/R2: occupancy is non-binding
// (40% occ == 82% occ == ~5.95 TB/s); kernel is at the mixed-R/W HBM
// ceiling. MLP=8 + evict-first is the only untried combination.

#define B_ 8
#define S_ 4096
#define D_ 1024
#define SD4_ ((S_ * D_) / 4)   // 1,048,576 float4 tiles per batch slice

__global__ __launch_bounds__(256) void pe_add_kernel(
    const float4* __restrict__ x, float4* __restrict__ out)
{
    const int idx4 = blockIdx.x * blockDim.x + threadIdx.x;   // [0, SD4_)
    const int d0   = (idx4 & (D_ / 4 - 1)) << 2;              // element column in D
    const float sf = (float)(idx4 >> 8);                      // s = idx4 / 256

    // Front-batch all 8 batch-slice loads -> 8 outstanding LDG.128 per thread.
    float4 v[B_];
#pragma unroll
    for (int b = 0; b < B_; b++)
        v[b] = __ldcs(x + (long long)b * SD4_ + idx4);

    // Encoding float4 (overlaps with the in-flight loads).
    // angle(d) = s * 10000^(-d/D) = s * exp2(-d * log2(1e4)/D)
    const float c = -(13.287712379549449f / 1024.0f);
    const float a0 = sf * exp2f((float)(d0 + 0) * c);
    const float a1 = sf * exp2f((float)(d0 + 1) * c);
    const float a2 = sf * exp2f((float)(d0 + 2) * c);
    const float a3 = sf * exp2f((float)(d0 + 3) * c);
    const float e0 = sinf(a0);   // even d -> sin
    const float e1 = cosf(a1);   // odd d  -> cos
    const float e2 = sinf(a2);
    const float e3 = cosf(a3);

#pragma unroll
    for (int b = 0; b < B_; b++) {
        float4 r = v[b];
        r.x += e0; r.y += e1; r.z += e2; r.w += e3;
        __stcs(out + (long long)b * SD4_ + idx4, r);
    }
}

extern "C" void kernel_launch(void* const* d_in, const int* in_sizes, int n_in,
                              void* d_out, int out_size)
{
    const float4* x = (const float4*)d_in[0];
    float4* out = (float4*)d_out;
    pe_add_kernel<<<SD4_ / 256, 256>>>(x, out);
}